// round 13
// baseline (speedup 1.0000x reference)
#include <cuda_runtime.h>

#define N    8192
#define NZ   256
#define NC   128
#define TPB  256
#define RPB  4                  // rows per group (measured best)
#define NGRP (N / RPB)          // 2048 row-groups
#define PBLK 592                // persistent blocks = 4 per SM x 148 SMs
#define SPLZ 4                  // split-K for k_z (measured best)

__device__ float g_r[N];                   // r = tanh(x+b)
__device__ float g_zpart[SPLZ][NZ];        // split partials of z = W_rz @ r
__device__ int   g_ticket;                 // work ticket for persistent update

__device__ __forceinline__ float warp_red(float v) {
    #pragma unroll
    for (int o = 16; o; o >>= 1) v += __shfl_down_sync(0xffffffffu, v, o);
    return v;
}

__device__ __forceinline__ float block_reduce(float v) {
    __shared__ float sm[TPB / 32];
    int lane = threadIdx.x & 31, wid = threadIdx.x >> 5;
    v = warp_red(v);
    if (lane == 0) sm[wid] = v;
    __syncthreads();
    if (wid == 0) {
        v = (lane < TPB / 32) ? sm[lane] : 0.0f;
        v = warp_red(v);
    }
    return v;  // valid in thread 0
}

__device__ __forceinline__ void block_reduceN(float* s) {
    __shared__ float sm[RPB][TPB / 32];
    int lane = threadIdx.x & 31, wid = threadIdx.x >> 5;
    #pragma unroll
    for (int k = 0; k < RPB; k++) {
        float v = warp_red(s[k]);
        if (lane == 0) sm[k][wid] = v;
    }
    __syncthreads();
    if (wid == 0) {
        #pragma unroll
        for (int k = 0; k < RPB; k++) {
            float v = (lane < TPB / 32) ? sm[k][lane] : 0.0f;
            s[k] = warp_red(v);   // valid in lane 0
        }
    }
}

__device__ __forceinline__ float dot4(float4 w, float4 v, float s) {
    return fmaf(w.x, v.x, fmaf(w.y, v.y, fmaf(w.z, v.z, fmaf(w.w, v.w, s))));
}

// ── Kernel 1: r = tanh(x + b); reset the update ticket. ──
__global__ void k_rate(const float* __restrict__ x, const float* __restrict__ b) {
    int i = blockIdx.x * blockDim.x + threadIdx.x;
    if (i < N) g_r[i] = tanhf(x[i] + b[i]);
    if (i == 0) g_ticket = 0;
}

// ── Kernel 2: z partials (exact R4 shape). grid = NZ*SPLZ = 1024. ──
__global__ void k_z(const float* __restrict__ W_rz) {
    int row  = blockIdx.x >> 2;        // SPLZ == 4
    int part = blockIdx.x & 3;
    const int C4 = N / 4 / SPLZ;       // 512 float4 per part
    const float4* W4 = reinterpret_cast<const float4*>(W_rz + (size_t)row * N) + part * C4;
    const float4* r4 = reinterpret_cast<const float4*>(g_r) + part * C4;
    int t = threadIdx.x;
    float4 w0 = __ldcs(&W4[t]);
    float4 w1 = __ldcs(&W4[t + TPB]);
    float4 r0 = r4[t];
    float4 r1 = r4[t + TPB];
    float s = dot4(w0, r0, 0.0f);
    s = dot4(w1, r1, s);
    s = block_reduce(s);
    if (t == 0) g_zpart[part][row] = s;
}

// ── Kernel 3: persistent fused Euler update. grid = PBLK = 592 (4/SM,
// single uniform wave); blocks pull RPB-row groups off a global ticket. ──
__global__ void __launch_bounds__(TPB) k_update(
                         const float* __restrict__ x,
                         const float* __restrict__ b,
                         const float* __restrict__ eps,
                         const float* __restrict__ c,
                         const float* __restrict__ W_rr,
                         const float* __restrict__ W_zr,
                         const float* __restrict__ W_cr,
                         const float* __restrict__ W_epsr,
                         float* __restrict__ out) {
    const float4* r4 = reinterpret_cast<const float4*>(g_r);
    const size_t RS = N / 4;  // row stride in float4

    // hoist small operands: eps, summed z, c (constant across groups)
    float4 ev = make_float4(0.f,0.f,0.f,0.f), zv = make_float4(0.f,0.f,0.f,0.f);
    float4 cv = make_float4(0.f,0.f,0.f,0.f);
    if (threadIdx.x < NZ / 4) {
        int j = threadIdx.x;
        ev = reinterpret_cast<const float4*>(eps)[j];
        #pragma unroll
        for (int p = 0; p < SPLZ; p++) {
            float4 a = reinterpret_cast<const float4*>(g_zpart[p])[j];
            zv.x += a.x; zv.y += a.y; zv.z += a.z; zv.w += a.w;
        }
    }
    if (threadIdx.x < NC / 4)
        cv = reinterpret_cast<const float4*>(c)[threadIdx.x];

    __shared__ int sh_g;
    for (;;) {
        if (threadIdx.x == 0) sh_g = atomicAdd(&g_ticket, 1);
        __syncthreads();
        int g = sh_g;
        if (g >= NGRP) return;

        int row0 = g * RPB;
        const float4* W0 = reinterpret_cast<const float4*>(W_rr + (size_t)row0 * N);

        float s[RPB] = {0.f, 0.f, 0.f, 0.f};
        #pragma unroll 2
        for (int j = threadIdx.x; j < N / 4; j += TPB) {
            float4 rv = r4[j];
            #pragma unroll
            for (int k = 0; k < RPB; k++) {
                float4 w = __ldcs(&W0[(size_t)k * RS + j]);
                s[k] = dot4(w, rv, s[k]);
            }
        }

        if (threadIdx.x < NZ / 4) {
            int j = threadIdx.x;
            #pragma unroll
            for (int k = 0; k < RPB; k++) {
                const float4* We = reinterpret_cast<const float4*>(W_epsr + (size_t)(row0 + k) * NZ);
                const float4* Wz = reinterpret_cast<const float4*>(W_zr   + (size_t)(row0 + k) * NZ);
                float4 we = __ldcs(&We[j]);
                float4 wz = __ldcs(&Wz[j]);
                s[k] = dot4(we, ev, s[k]);
                s[k] = dot4(wz, zv, s[k]);
            }
        }
        if (threadIdx.x < NC / 4) {
            int j = threadIdx.x;
            #pragma unroll
            for (int k = 0; k < RPB; k++) {
                const float4* Wc = reinterpret_cast<const float4*>(W_cr + (size_t)(row0 + k) * NC);
                float4 wc = __ldcs(&Wc[j]);
                s[k] = dot4(wc, cv, s[k]);
            }
        }

        block_reduceN(s);
        if (threadIdx.x == 0) {
            #pragma unroll
            for (int k = 0; k < RPB; k++) {
                int row = row0 + k;
                float xi = x[row];
                float xn = xi + 0.1f * (-xi + s[k]);   // dt=0.1, tau=1
                out[row] = xn;
                out[N + row] = tanhf(xn + b[row]);
            }
        }
        __syncthreads();   // protect sh_g / reduce smem reuse
    }
}

// ── Kernel 4: readout, un-split, direct write (no k_final). grid = 384. ──
__global__ void k_readout(const float* __restrict__ W_rz,
                          const float* __restrict__ W_rc,
                          const float* __restrict__ z_tilde,
                          float* __restrict__ out) {
    int row = blockIdx.x;
    const float* Wrow = (row < NZ) ? (W_rz + (size_t)row * N)
                                   : (W_rc + (size_t)(row - NZ) * N);
    const float4* W4 = reinterpret_cast<const float4*>(Wrow);
    const float4* r4 = reinterpret_cast<const float4*>(out + N);  // r_new
    int t = threadIdx.x;
    float s = 0.0f;
    #pragma unroll
    for (int u = 0; u < N / 4 / TPB; u++) {   // 8 independent load pairs
        float4 w = __ldcs(&W4[t + u * TPB]);
        float4 r = r4[t + u * TPB];
        s = dot4(w, r, s);
    }
    s = block_reduce(s);
    if (t == 0) {
        if (row < NZ) {
            out[2 * N + row] = s;                          // z_new
            out[2 * N + NZ + NC + row] = s - z_tilde[row]; // eps_new
        } else {
            out[2 * N + NZ + (row - NZ)] = s;              // c_new
        }
    }
}

extern "C" void kernel_launch(void* const* d_in, const int* in_sizes, int n_in,
                              void* d_out, int out_size) {
    const float* x       = (const float*)d_in[0];
    const float* eps     = (const float*)d_in[1];
    const float* c       = (const float*)d_in[2];
    const float* z_tilde = (const float*)d_in[3];
    const float* W_rr    = (const float*)d_in[4];
    const float* W_zr    = (const float*)d_in[5];
    const float* W_cr    = (const float*)d_in[6];
    const float* W_epsr  = (const float*)d_in[7];
    const float* W_rz    = (const float*)d_in[8];
    const float* W_rc    = (const float*)d_in[9];
    const float* b       = (const float*)d_in[10];
    float* out = (float*)d_out;

    k_rate<<<(N + TPB - 1) / TPB, TPB>>>(x, b);
    k_z<<<NZ * SPLZ, TPB>>>(W_rz);
    k_update<<<PBLK, TPB>>>(x, b, eps, c, W_rr, W_zr, W_cr, W_epsr, out);
    k_readout<<<NZ + NC, TPB>>>(W_rz, W_rc, z_tilde, out);
}

// round 14
// speedup vs baseline: 1.1391x; 1.1391x over previous
#include <cuda_runtime.h>

#define N    8192
#define NZ   256
#define NC   128
#define TPB  256
#define RPB  4                  // rows per block in k_update (measured best)
#define SPLZ 4                  // split-K for k_z (measured best)

__device__ float g_r[N];                   // r = tanh(x+b)
__device__ float g_zpart[SPLZ][NZ];        // split partials of z = W_rz @ r

__device__ __forceinline__ float warp_red(float v) {
    #pragma unroll
    for (int o = 16; o; o >>= 1) v += __shfl_down_sync(0xffffffffu, v, o);
    return v;
}

__device__ __forceinline__ float block_reduce(float v) {
    __shared__ float sm[TPB / 32];
    int lane = threadIdx.x & 31, wid = threadIdx.x >> 5;
    v = warp_red(v);
    if (lane == 0) sm[wid] = v;
    __syncthreads();
    if (wid == 0) {
        v = (lane < TPB / 32) ? sm[lane] : 0.0f;
        v = warp_red(v);
    }
    return v;  // valid in thread 0
}

__device__ __forceinline__ void block_reduceN(float* s) {
    __shared__ float sm[RPB][TPB / 32];
    int lane = threadIdx.x & 31, wid = threadIdx.x >> 5;
    #pragma unroll
    for (int k = 0; k < RPB; k++) {
        float v = warp_red(s[k]);
        if (lane == 0) sm[k][wid] = v;
    }
    __syncthreads();
    if (wid == 0) {
        #pragma unroll
        for (int k = 0; k < RPB; k++) {
            float v = (lane < TPB / 32) ? sm[k][lane] : 0.0f;
            s[k] = warp_red(v);   // valid in lane 0
        }
    }
}

__device__ __forceinline__ float dot4(float4 w, float4 v, float s) {
    return fmaf(w.x, v.x, fmaf(w.y, v.y, fmaf(w.z, v.z, fmaf(w.w, v.w, s))));
}

// ── Kernel 1: r = tanh(x + b). ──
__global__ void k_rate(const float* __restrict__ x, const float* __restrict__ b) {
    int i = blockIdx.x * blockDim.x + threadIdx.x;
    if (i < N) g_r[i] = tanhf(x[i] + b[i]);
}

// ── Kernel 2: z partials (exact R4 shape). grid = NZ*SPLZ = 1024. ──
__global__ void k_z(const float* __restrict__ W_rz) {
    int row  = blockIdx.x >> 2;        // SPLZ == 4
    int part = blockIdx.x & 3;
    const int C4 = N / 4 / SPLZ;       // 512 float4 per part
    const float4* W4 = reinterpret_cast<const float4*>(W_rz + (size_t)row * N) + part * C4;
    const float4* r4 = reinterpret_cast<const float4*>(g_r) + part * C4;
    int t = threadIdx.x;
    float4 w0 = __ldcs(&W4[t]);
    float4 w1 = __ldcs(&W4[t + TPB]);
    float4 r0 = r4[t];
    float4 r1 = r4[t + TPB];
    float s = dot4(w0, r0, 0.0f);
    s = dot4(w1, r1, s);
    s = block_reduce(s);
    if (t == 0) g_zpart[part][row] = s;
}

// ── Kernel 3: fused Euler update, RPB=4, grid 2048; r staged in smem. ──
__global__ void __launch_bounds__(TPB) k_update(
                         const float* __restrict__ x,
                         const float* __restrict__ b,
                         const float* __restrict__ eps,
                         const float* __restrict__ c,
                         const float* __restrict__ W_rr,
                         const float* __restrict__ W_zr,
                         const float* __restrict__ W_cr,
                         const float* __restrict__ W_epsr,
                         float* __restrict__ out) {
    __shared__ float4 sh_r[N / 4];     // 32 KB: r staged once per block

    int row0 = blockIdx.x * RPB;
    const float4* r4 = reinterpret_cast<const float4*>(g_r);
    const float4* W0 = reinterpret_cast<const float4*>(W_rr + (size_t)row0 * N);
    const size_t RS = N / 4;  // row stride in float4

    // cooperative stage of r into shared (8 float4 per thread)
    #pragma unroll
    for (int u = 0; u < N / 4 / TPB; u++)
        sh_r[threadIdx.x + u * TPB] = r4[threadIdx.x + u * TPB];
    __syncthreads();

    float s[RPB] = {0.f, 0.f, 0.f, 0.f};
    #pragma unroll 2
    for (int j = threadIdx.x; j < N / 4; j += TPB) {
        float4 rv = sh_r[j];
        #pragma unroll
        for (int k = 0; k < RPB; k++) {
            float4 w = __ldcs(&W0[(size_t)k * RS + j]);
            s[k] = dot4(w, rv, s[k]);
        }
    }

    // tails: W_epsr @ eps, W_zr @ z, W_cr @ c
    if (threadIdx.x < NZ / 4) {
        int j = threadIdx.x;
        float4 ev = reinterpret_cast<const float4*>(eps)[j];
        float4 zv = make_float4(0.f, 0.f, 0.f, 0.f);
        #pragma unroll
        for (int p = 0; p < SPLZ; p++) {
            float4 a = reinterpret_cast<const float4*>(g_zpart[p])[j];
            zv.x += a.x; zv.y += a.y; zv.z += a.z; zv.w += a.w;
        }
        #pragma unroll
        for (int k = 0; k < RPB; k++) {
            const float4* We = reinterpret_cast<const float4*>(W_epsr + (size_t)(row0 + k) * NZ);
            const float4* Wz = reinterpret_cast<const float4*>(W_zr   + (size_t)(row0 + k) * NZ);
            float4 we = __ldcs(&We[j]);
            float4 wz = __ldcs(&Wz[j]);
            s[k] = dot4(we, ev, s[k]);
            s[k] = dot4(wz, zv, s[k]);
        }
    }
    if (threadIdx.x < NC / 4) {
        int j = threadIdx.x;
        float4 cv = reinterpret_cast<const float4*>(c)[j];
        #pragma unroll
        for (int k = 0; k < RPB; k++) {
            const float4* Wc = reinterpret_cast<const float4*>(W_cr + (size_t)(row0 + k) * NC);
            float4 wc = __ldcs(&Wc[j]);
            s[k] = dot4(wc, cv, s[k]);
        }
    }

    block_reduceN(s);
    if (threadIdx.x == 0) {
        #pragma unroll
        for (int k = 0; k < RPB; k++) {
            int row = row0 + k;
            float xi = x[row];
            float xn = xi + 0.1f * (-xi + s[k]);   // dt=0.1, tau=1
            out[row] = xn;
            out[N + row] = tanhf(xn + b[row]);
        }
    }
}

// ── Kernel 4: readout, un-split, direct write (no k_final). grid = 384. ──
__global__ void k_readout(const float* __restrict__ W_rz,
                          const float* __restrict__ W_rc,
                          const float* __restrict__ z_tilde,
                          float* __restrict__ out) {
    int row = blockIdx.x;
    const float* Wrow = (row < NZ) ? (W_rz + (size_t)row * N)
                                   : (W_rc + (size_t)(row - NZ) * N);
    const float4* W4 = reinterpret_cast<const float4*>(Wrow);
    const float4* r4 = reinterpret_cast<const float4*>(out + N);  // r_new
    int t = threadIdx.x;
    float s = 0.0f;
    #pragma unroll
    for (int u = 0; u < N / 4 / TPB; u++) {   // 8 independent load pairs
        float4 w = __ldcs(&W4[t + u * TPB]);
        float4 r = r4[t + u * TPB];
        s = dot4(w, r, s);
    }
    s = block_reduce(s);
    if (t == 0) {
        if (row < NZ) {
            out[2 * N + row] = s;                          // z_new
            out[2 * N + NZ + NC + row] = s - z_tilde[row]; // eps_new
        } else {
            out[2 * N + NZ + (row - NZ)] = s;              // c_new
        }
    }
}

extern "C" void kernel_launch(void* const* d_in, const int* in_sizes, int n_in,
                              void* d_out, int out_size) {
    const float* x       = (const float*)d_in[0];
    const float* eps     = (const float*)d_in[1];
    const float* c       = (const float*)d_in[2];
    const float* z_tilde = (const float*)d_in[3];
    const float* W_rr    = (const float*)d_in[4];
    const float* W_zr    = (const float*)d_in[5];
    const float* W_cr    = (const float*)d_in[6];
    const float* W_epsr  = (const float*)d_in[7];
    const float* W_rz    = (const float*)d_in[8];
    const float* W_rc    = (const float*)d_in[9];
    const float* b       = (const float*)d_in[10];
    float* out = (float*)d_out;

    k_rate<<<(N + TPB - 1) / TPB, TPB>>>(x, b);
    k_z<<<NZ * SPLZ, TPB>>>(W_rz);
    k_update<<<N / RPB, TPB>>>(x, b, eps, c, W_rr, W_zr, W_cr, W_epsr, out);
    k_readout<<<NZ + NC, TPB>>>(W_rz, W_rc, z_tilde, out);
}